// round 2
// baseline (speedup 1.0000x reference)
#include <cuda_runtime.h>

// ---------------------------------------------------------------------------
// HGTransformerLayer — fp32, edge-type factorized (t in {0,1}).
//   k[b,n] = Kbase[n] + KE[t],  v[b,n] = Vbase[n] + VE[t]
// so scores and AV decompose; the [1024,1024,256] msg tensor never exists.
// ---------------------------------------------------------------------------

#define SCALE_Q 0.17677669529663687f  // 1/sqrt(32)

// scratch (no allocations allowed)
__device__ float g_Q[1024 * 256];   // scaled Q
__device__ float g_K[1024 * 256];   // Kbase
__device__ float g_V[1024 * 256];   // Vbase
__device__ float g_KE[2 * 256];
__device__ float g_VE[2 * 256];
__device__ float g_AO[1024 * 256];  // attention output

// ---------------------------------------------------------------------------
// fp32 GEMM: C[M,256] = (A[M,256] @ W[256,256]^T + bias) * scale
// BM=32, BN=64, BK=16, 128 threads, 4x4 thread tile.
// ---------------------------------------------------------------------------
__device__ __forceinline__ void gemm_body(const float* __restrict__ A,
                                          const float* __restrict__ W,
                                          const float* __restrict__ bias,
                                          float* __restrict__ C, float scale)
{
    __shared__ float As[16][36];
    __shared__ float Ws[16][68];

    const int tid = threadIdx.x;
    const int m0 = blockIdx.x * 32;
    const int n0 = blockIdx.y * 64;
    const int tx = tid & 15;   // 4 cols each
    const int ty = tid >> 4;   // 4 rows each

    float acc[4][4];
#pragma unroll
    for (int i = 0; i < 4; ++i)
#pragma unroll
        for (int j = 0; j < 4; ++j) acc[i][j] = 0.f;

    for (int k0 = 0; k0 < 256; k0 += 16) {
        {
            int m = tid >> 2, kc = tid & 3;
            float4 v = *reinterpret_cast<const float4*>(&A[(m0 + m) * 256 + k0 + kc * 4]);
            As[kc * 4 + 0][m] = v.x; As[kc * 4 + 1][m] = v.y;
            As[kc * 4 + 2][m] = v.z; As[kc * 4 + 3][m] = v.w;
        }
#pragma unroll
        for (int it = 0; it < 2; ++it) {
            int idx = tid + it * 128;
            int n = idx >> 2, kc = idx & 3;
            float4 v = *reinterpret_cast<const float4*>(&W[(n0 + n) * 256 + k0 + kc * 4]);
            Ws[kc * 4 + 0][n] = v.x; Ws[kc * 4 + 1][n] = v.y;
            Ws[kc * 4 + 2][n] = v.z; Ws[kc * 4 + 3][n] = v.w;
        }
        __syncthreads();
#pragma unroll
        for (int k = 0; k < 16; ++k) {
            float4 a = *reinterpret_cast<const float4*>(&As[k][ty * 4]);
            float4 w = *reinterpret_cast<const float4*>(&Ws[k][tx * 4]);
            float av[4] = {a.x, a.y, a.z, a.w};
            float wv[4] = {w.x, w.y, w.z, w.w};
#pragma unroll
            for (int i = 0; i < 4; ++i)
#pragma unroll
                for (int j = 0; j < 4; ++j) acc[i][j] += av[i] * wv[j];
        }
        __syncthreads();
    }
#pragma unroll
    for (int i = 0; i < 4; ++i) {
        int m = m0 + ty * 4 + i;
#pragma unroll
        for (int j = 0; j < 4; ++j) {
            int n = n0 + tx * 4 + j;
            C[m * 256 + n] = (acc[i][j] + bias[n]) * scale;
        }
    }
}

__global__ void qkv_kernel(const float* __restrict__ hT, const float* __restrict__ hN,
                           const float* __restrict__ Wq, const float* __restrict__ bq,
                           const float* __restrict__ Wk, const float* __restrict__ bk,
                           const float* __restrict__ Wv, const float* __restrict__ bv)
{
    if (blockIdx.z == 0)      gemm_body(hT, Wq, bq, g_Q, SCALE_Q);
    else if (blockIdx.z == 1) gemm_body(hN, Wk, bk, g_K, 1.f);
    else                      gemm_body(hN, Wv, bv, g_V, 1.f);
}

__global__ void proj_kernel(const float* __restrict__ Wo, const float* __restrict__ bo,
                            float* __restrict__ out)
{
    gemm_body(g_AO, Wo, bo, out, 1.f);
}

// KE[t] = E[t]@Wk^T, VE[t] = E[t]@Wv^T (no bias). 4 blocks x 256 thr.
__global__ void edge_kernel(const float* __restrict__ E, const float* __restrict__ Wk,
                            const float* __restrict__ Wv)
{
    const int t = blockIdx.x & 1;
    const int isv = blockIdx.x >> 1;
    const float* W = isv ? Wv : Wk;
    float* out = isv ? g_VE : g_KE;

    __shared__ float e[256];
    e[threadIdx.x] = E[t * 256 + threadIdx.x];
    __syncthreads();

    const int warp = threadIdx.x >> 5, lane = threadIdx.x & 31;
    for (int d = warp; d < 256; d += 8) {
        float acc = 0.f;
        for (int k = lane; k < 256; k += 32) acc += e[k] * W[d * 256 + k];
#pragma unroll
        for (int m = 16; m; m >>= 1) acc += __shfl_xor_sync(0xffffffffu, acc, m);
        if (lane == 0) out[t * 256 + d] = acc;
    }
}

// ---------------------------------------------------------------------------
// Fused attention: grid (64 row-tiles, 8 heads), 256 threads.
// 16 rows/CTA. Warp w owns rows {2w, 2w+1}; lane l owns n = l + 32*i, i<32.
// Full per-head K (1024x32, pad 33) in smem, buffer reused for V, then for
// the AV cross-lane reduction.
// ---------------------------------------------------------------------------
#define SK_F (1024 * 33)
__global__ __launch_bounds__(256, 1)
void attn_kernel(const int* __restrict__ adj, const int* __restrict__ et)
{
    extern __shared__ float sm[];
    float* sK  = sm;                 // 33792 f (K, then V, then reduction)
    float* sQ  = sm + SK_F;          // 16*33 = 528
    float* sqe = sQ + 528;           // 32
    float* sKE = sqe + 32;           // 64
    float* sVE = sKE + 64;           // 64
    float* sw  = sVE + 64;           // 32

    const int tid = threadIdx.x;
    const int h = blockIdx.y;
    const int b0 = blockIdx.x << 4;
    const int l = tid & 31;
    const int rp = tid >> 5;          // 0..7
    const int row0 = rp * 2, row1 = rp * 2 + 1;

    // Q head slice [16][32]
#pragma unroll
    for (int j = 0; j < 2; ++j) {
        int idx = tid + (j << 8);
        int row = idx >> 5, d = idx & 31;
        sQ[row * 33 + d] = g_Q[(b0 + row) * 256 + h * 32 + d];
    }
    if (tid < 64) {
        int t = tid >> 5, d = tid & 31;
        sKE[tid] = g_KE[t * 256 + h * 32 + d];
        sVE[tid] = g_VE[t * 256 + h * 32 + d];
    }
    // K head slice [1024][32] -> pad-33
#pragma unroll
    for (int it = 0; it < 32; ++it) {
        int f4 = tid + (it << 8);
        int n = f4 >> 3, d4 = f4 & 7;
        float4 v = *reinterpret_cast<const float4*>(&g_K[n * 256 + h * 32 + d4 * 4]);
        float* p = &sK[n * 33 + d4 * 4];
        p[0] = v.x; p[1] = v.y; p[2] = v.z; p[3] = v.w;
    }
    __syncthreads();

    // qe[row][t] = Q[row] . KE[t]
    if (tid < 32) {
        int rr = tid >> 1, t = tid & 1;
        float a = 0.f;
#pragma unroll
        for (int d = 0; d < 32; ++d) a += sQ[rr * 33 + d] * sKE[t * 32 + d];
        sqe[rr * 2 + t] = a;
    }
    __syncthreads();

    // Q into registers for both rows
    float qd0[32], qd1[32];
#pragma unroll
    for (int d = 0; d < 32; ++d) { qd0[d] = sQ[row0 * 33 + d]; qd1[d] = sQ[row1 * 33 + d]; }
    const float qe00 = sqe[row0 * 2 + 0], qe01 = sqe[row0 * 2 + 1];
    const float qe10 = sqe[row1 * 2 + 0], qe11 = sqe[row1 * 2 + 1];

    const int* arow0 = adj + (b0 + row0) * 1024;
    const int* arow1 = adj + (b0 + row1) * 1024;
    const int* trow0 = et + (b0 + row0) * 1024;
    const int* trow1 = et + (b0 + row1) * 1024;

    float sc0[32], sc1[32];
    unsigned vb0 = 0, vb1 = 0, tb0 = 0, tb1 = 0;

#pragma unroll
    for (int i = 0; i < 32; ++i) {
        int n = l + (i << 5);
        int av0 = arow0[n], av1 = arow1[n];
        int t0 = trow0[n], t1 = trow1[n];
        float s0 = t0 ? qe01 : qe00;
        float s1 = t1 ? qe11 : qe10;
        const float* kp = &sK[n * 33];
#pragma unroll
        for (int d = 0; d < 32; ++d) {
            float kv = kp[d];
            s0 += qd0[d] * kv;
            s1 += qd1[d] * kv;
        }
        sc0[i] = s0; sc1[i] = s1;
        if (av0) vb0 |= 1u << i;
        if (av1) vb1 |= 1u << i;
        if (t0)  tb0 |= 1u << i;
        if (t1)  tb1 |= 1u << i;
    }

    // row max over valid entries
    float m0 = -3.0e38f, m1 = -3.0e38f;
#pragma unroll
    for (int i = 0; i < 32; ++i) {
        if ((vb0 >> i) & 1u) m0 = fmaxf(m0, sc0[i]);
        if ((vb1 >> i) & 1u) m1 = fmaxf(m1, sc1[i]);
    }
#pragma unroll
    for (int s = 16; s; s >>= 1) {
        m0 = fmaxf(m0, __shfl_xor_sync(0xffffffffu, m0, s));
        m1 = fmaxf(m1, __shfl_xor_sync(0xffffffffu, m1, s));
    }

    float sum0 = 0.f, sum1 = 0.f, w1s0 = 0.f, w1s1 = 0.f;
#pragma unroll
    for (int i = 0; i < 32; ++i) {
        float p0 = ((vb0 >> i) & 1u) ? __expf(sc0[i] - m0) : 0.f;
        float p1 = ((vb1 >> i) & 1u) ? __expf(sc1[i] - m1) : 0.f;
        sc0[i] = p0; sc1[i] = p1;
        sum0 += p0; sum1 += p1;
        if ((tb0 >> i) & 1u) w1s0 += p0;
        if ((tb1 >> i) & 1u) w1s1 += p1;
    }
#pragma unroll
    for (int s = 16; s; s >>= 1) {
        sum0 += __shfl_xor_sync(0xffffffffu, sum0, s);
        sum1 += __shfl_xor_sync(0xffffffffu, sum1, s);
        w1s0 += __shfl_xor_sync(0xffffffffu, w1s0, s);
        w1s1 += __shfl_xor_sync(0xffffffffu, w1s1, s);
    }
    const float inv0 = sum0 > 0.f ? 1.f / sum0 : 0.f;
    const float inv1 = sum1 > 0.f ? 1.f / sum1 : 0.f;
#pragma unroll
    for (int i = 0; i < 32; ++i) { sc0[i] *= inv0; sc1[i] *= inv1; }
    if (l == 0) {
        sw[row0 * 2 + 0] = (sum0 - w1s0) * inv0;
        sw[row0 * 2 + 1] = w1s0 * inv0;
        sw[row1 * 2 + 0] = (sum1 - w1s1) * inv1;
        sw[row1 * 2 + 1] = w1s1 * inv1;
    }

    // reload buffer with V
    __syncthreads();
#pragma unroll
    for (int it = 0; it < 32; ++it) {
        int f4 = tid + (it << 8);
        int n = f4 >> 3, d4 = f4 & 7;
        float4 v = *reinterpret_cast<const float4*>(&g_V[n * 256 + h * 32 + d4 * 4]);
        float* p = &sK[n * 33 + d4 * 4];
        p[0] = v.x; p[1] = v.y; p[2] = v.z; p[3] = v.w;
    }
    __syncthreads();

    float ac0[32], ac1[32];
#pragma unroll
    for (int d = 0; d < 32; ++d) { ac0[d] = 0.f; ac1[d] = 0.f; }
#pragma unroll
    for (int i = 0; i < 32; ++i) {
        float a0 = sc0[i], a1 = sc1[i];
        const float* vp = &sK[(l + (i << 5)) * 33];
#pragma unroll
        for (int d = 0; d < 32; ++d) {
            float vv = vp[d];
            ac0[d] += a0 * vv;
            ac1[d] += a1 * vv;
        }
    }

    // cross-lane reduce via recycled buffer: red[(row*32+lane)*33 + d]
    __syncthreads();
#pragma unroll
    for (int d = 0; d < 32; ++d) {
        sK[(row0 * 32 + l) * 33 + d] = ac0[d];
        sK[(row1 * 32 + l) * 33 + d] = ac1[d];
    }
    __syncthreads();

#pragma unroll
    for (int j = 0; j < 2; ++j) {
        int idx = tid + (j << 8);
        int row = idx >> 5, d = idx & 31;
        float o = 0.f;
#pragma unroll
        for (int s = 0; s < 32; ++s) {
            int ll = (s + ((row & 7) << 2)) & 31;   // stagger: kills bank conflicts
            o += sK[(row * 32 + ll) * 33 + d];
        }
        o += sw[row * 2 + 0] * sVE[d] + sw[row * 2 + 1] * sVE[32 + d];
        g_AO[(b0 + row) * 256 + h * 32 + d] = o;
    }
}

// ---------------------------------------------------------------------------
extern "C" void kernel_launch(void* const* d_in, const int* in_sizes, int n_in,
                              void* d_out, int out_size)
{
    const float* h_target = (const float*)d_in[0];
    const float* h_neigh  = (const float*)d_in[1];
    const int*   adjacency = (const int*)d_in[2];
    const int*   edge_types = (const int*)d_in[3];
    const float* Wq = (const float*)d_in[4];
    const float* bq = (const float*)d_in[5];
    const float* Wk = (const float*)d_in[6];
    const float* bk = (const float*)d_in[7];
    const float* Wv = (const float*)d_in[8];
    const float* bv = (const float*)d_in[9];
    const float* Wo = (const float*)d_in[10];
    const float* bo = (const float*)d_in[11];
    const float* E  = (const float*)d_in[12];
    float* out = (float*)d_out;

    static int smem_set = 0;
    const int attn_smem = (SK_F + 528 + 32 + 64 + 64 + 32) * 4;  // 138048 B
    if (!smem_set) {
        cudaFuncSetAttribute(attn_kernel, cudaFuncAttributeMaxDynamicSharedMemorySize,
                             attn_smem);
        smem_set = 1;
    }

    qkv_kernel<<<dim3(32, 4, 3), 128>>>(h_target, h_neigh, Wq, bq, Wk, bk, Wv, bv);
    edge_kernel<<<4, 256>>>(E, Wk, Wv);
    attn_kernel<<<dim3(64, 8), 256, attn_smem>>>(adjacency, edge_types);
    proj_kernel<<<dim3(32, 4), 128>>>(Wo, bo, out);
}

// round 3
// speedup vs baseline: 1.7339x; 1.7339x over previous
#include <cuda_runtime.h>

// ---------------------------------------------------------------------------
// HGTransformerLayer — fp32, edge-type factorized (t in {0,1}).
//   k[b,n] = Kbase[n] + KE[t],  v[b,n] = Vbase[n] + VE[t]
// scores[b,h,n] = Qs[b,h].Kbase[n,h] + qe[b,h,t];  out adds w0*VE0 + w1*VE1.
// f32x2 (FFMA2) used for both score and AV inner loops.
// ---------------------------------------------------------------------------

#define SCALE_Q 0.17677669529663687f  // 1/sqrt(32)

// scratch (no allocations allowed)
__device__ float g_Q[1024 * 256];   // [h][b][32], scaled
__device__ float g_K[1024 * 256];   // [h][n][32]
__device__ float g_V[1024 * 256];   // [h][n][32]
__device__ float g_KE[2 * 256];
__device__ float g_VE[2 * 256];
__device__ float g_AO[1024 * 256];  // row-major [b][256]
__device__ unsigned g_mba[1024 * 2 * 32];  // adjacency bitmask [(row*2+half)*32 + lane]
__device__ unsigned g_mbt[1024 * 2 * 32];  // edge-type bitmask

#define FMA2(acc, a, b) \
    asm("fma.rn.f32x2 %0, %1, %2, %3;" : "=l"(acc) : "l"(a), "l"(b), "l"(acc))

__device__ __forceinline__ unsigned long long bcast2(float x) {
    unsigned long long r;
    asm("mov.b64 %0, {%1, %1};" : "=l"(r) : "f"(x));
    return r;
}
__device__ __forceinline__ float2 unpack2(unsigned long long v) {
    float2 f;
    asm("mov.b64 {%0, %1}, %2;" : "=f"(f.x), "=f"(f.y) : "l"(v));
    return f;
}

// ---------------------------------------------------------------------------
// fp32 GEMM: C = (A[M,256] @ W[256,256]^T + bias) * scale
// BM=32, BN=64, BK=16, 128 threads, 4x4 tile, register double-buffered.
// headmode: write C as [h][m][32] slices instead of row-major.
// ---------------------------------------------------------------------------
__device__ __forceinline__ void gemm_body(const float* __restrict__ A,
                                          const float* __restrict__ W,
                                          const float* __restrict__ bias,
                                          float* __restrict__ C, float scale,
                                          bool headmode)
{
    __shared__ float As[16][36];
    __shared__ float Ws[16][68];

    const int tid = threadIdx.x;
    const int m0 = blockIdx.x * 32;
    const int n0 = blockIdx.y * 64;
    const int tx = tid & 15;
    const int ty = tid >> 4;
    const int am = tid >> 2, ak = tid & 3;

    float4 ra  = *reinterpret_cast<const float4*>(&A[(m0 + am) * 256 + ak * 4]);
    float4 rw0 = *reinterpret_cast<const float4*>(&W[(n0 + am) * 256 + ak * 4]);
    float4 rw1 = *reinterpret_cast<const float4*>(&W[(n0 + am + 32) * 256 + ak * 4]);

    float acc[4][4];
#pragma unroll
    for (int i = 0; i < 4; ++i)
#pragma unroll
        for (int j = 0; j < 4; ++j) acc[i][j] = 0.f;

    for (int k0 = 0; k0 < 256; k0 += 16) {
        As[ak * 4 + 0][am] = ra.x; As[ak * 4 + 1][am] = ra.y;
        As[ak * 4 + 2][am] = ra.z; As[ak * 4 + 3][am] = ra.w;
        Ws[ak * 4 + 0][am] = rw0.x; Ws[ak * 4 + 1][am] = rw0.y;
        Ws[ak * 4 + 2][am] = rw0.z; Ws[ak * 4 + 3][am] = rw0.w;
        Ws[ak * 4 + 0][am + 32] = rw1.x; Ws[ak * 4 + 1][am + 32] = rw1.y;
        Ws[ak * 4 + 2][am + 32] = rw1.z; Ws[ak * 4 + 3][am + 32] = rw1.w;
        __syncthreads();
        if (k0 + 16 < 256) {
            ra  = *reinterpret_cast<const float4*>(&A[(m0 + am) * 256 + k0 + 16 + ak * 4]);
            rw0 = *reinterpret_cast<const float4*>(&W[(n0 + am) * 256 + k0 + 16 + ak * 4]);
            rw1 = *reinterpret_cast<const float4*>(&W[(n0 + am + 32) * 256 + k0 + 16 + ak * 4]);
        }
#pragma unroll
        for (int k = 0; k < 16; ++k) {
            float4 a4 = *reinterpret_cast<const float4*>(&As[k][ty * 4]);
            float4 w4 = *reinterpret_cast<const float4*>(&Ws[k][tx * 4]);
            float av[4] = {a4.x, a4.y, a4.z, a4.w};
            float wv[4] = {w4.x, w4.y, w4.z, w4.w};
#pragma unroll
            for (int i = 0; i < 4; ++i)
#pragma unroll
                for (int j = 0; j < 4; ++j) acc[i][j] += av[i] * wv[j];
        }
        __syncthreads();
    }
#pragma unroll
    for (int i = 0; i < 4; ++i) {
        int m = m0 + ty * 4 + i;
#pragma unroll
        for (int j = 0; j < 4; ++j) {
            int n = n0 + tx * 4 + j;
            float val = (acc[i][j] + bias[n]) * scale;
            if (headmode) C[(n >> 5) * 32768 + m * 32 + (n & 31)] = val;
            else          C[m * 256 + n] = val;
        }
    }
}

__global__ void qkv_kernel(const float* __restrict__ hT, const float* __restrict__ hN,
                           const float* __restrict__ Wq, const float* __restrict__ bq,
                           const float* __restrict__ Wk, const float* __restrict__ bk,
                           const float* __restrict__ Wv, const float* __restrict__ bv)
{
    if (blockIdx.z == 0)      gemm_body(hT, Wq, bq, g_Q, SCALE_Q, true);
    else if (blockIdx.z == 1) gemm_body(hN, Wk, bk, g_K, 1.f, true);
    else                      gemm_body(hN, Wv, bv, g_V, 1.f, true);
}

__global__ void proj_kernel(const float* __restrict__ Wo, const float* __restrict__ bo,
                            float* __restrict__ out)
{
    gemm_body(g_AO, Wo, bo, out, 1.f, false);
}

// KE[t] = E[t]@Wk^T, VE[t] = E[t]@Wv^T
__global__ void edge_kernel(const float* __restrict__ E, const float* __restrict__ Wk,
                            const float* __restrict__ Wv)
{
    const int t = blockIdx.x & 1;
    const int isv = blockIdx.x >> 1;
    const float* W = isv ? Wv : Wk;
    float* out = isv ? g_VE : g_KE;

    __shared__ float e[256];
    e[threadIdx.x] = E[t * 256 + threadIdx.x];
    __syncthreads();

    const int warp = threadIdx.x >> 5, lane = threadIdx.x & 31;
    for (int d = warp; d < 256; d += 8) {
        float acc = 0.f;
        for (int k = lane; k < 256; k += 32) acc += e[k] * W[d * 256 + k];
#pragma unroll
        for (int m = 16; m; m >>= 1) acc += __shfl_xor_sync(0xffffffffu, acc, m);
        if (lane == 0) out[t * 256 + d] = acc;
    }
}

// pack adj/et into per-(row,half,lane) 16-bit masks (bit ii = n = half*512+lane+32*ii)
__global__ void pack_kernel(const int* __restrict__ adj, const int* __restrict__ et)
{
    const int unit = blockIdx.x * 8 + (threadIdx.x >> 5);  // (row*2 + half)
    const int l = threadIdx.x & 31;
    const int row = unit >> 1, half = unit & 1;
    const int* ap = adj + row * 1024 + half * 512 + l;
    const int* tp = et  + row * 1024 + half * 512 + l;
    unsigned va = 0, vt = 0;
#pragma unroll
    for (int ii = 0; ii < 16; ++ii) {
        if (ap[ii * 32]) va |= 1u << ii;
        if (tp[ii * 32]) vt |= 1u << ii;
    }
    g_mba[unit * 32 + l] = va;
    g_mbt[unit * 32 + l] = vt;
}

// ---------------------------------------------------------------------------
// Fused attention: grid (64 row-tiles, 8 heads), 256 threads, 1 CTA/SM.
// warp w: g = w&3 -> rows 4g..4g+3; half = w>>2 -> n in [half*512, half*512+512).
// lane l: n = half*512 + l + 32*ii, ii<16.
// K/V slice [1024][34] in smem (LDS.64 conflict-free), scores in smem [16][1024].
// ---------------------------------------------------------------------------
#define SK_F (1024 * 34)
#define SS_F (16 * 1024)
#define SQ_F (16 * 34)

__global__ __launch_bounds__(256, 1)
void attn_kernel()
{
    extern __shared__ float sm[];
    float* sK   = sm;                        // K, then V, then reduction (34816 f)
    float* sS   = sK + SK_F;                 // scores/attn (16384 f)
    float* sQ   = sS + SS_F;                 // [16][34]
    float* sqe  = sQ + SQ_F;                 // [16][2]
    float* sKE  = sqe + 32;                  // [2][32]
    float* sVE  = sKE + 64;                  // [2][32]
    float* smax = sVE + 64;                  // [16][2]
    float* ssum = smax + 32;                 // [16][2]
    float* sw1  = ssum + 32;                 // [16][2]

    const int tid = threadIdx.x;
    const int h = blockIdx.y;
    const int b0 = blockIdx.x << 4;
    const int l = tid & 31;
    const int w = tid >> 5;
    const int g = w & 3;
    const int half = w >> 2;
    const int rbase = g << 2;
    const int nb = half * 512 + l;

    // ---- load K slice (contiguous 128KB) + Q + edge vecs ----
    {
        const float4* src = reinterpret_cast<const float4*>(g_K + h * 32768);
#pragma unroll
        for (int it = 0; it < 32; ++it) {
            int idx = tid + (it << 8);
            float4 v = src[idx];
            float* p = &sK[(idx >> 3) * 34 + (idx & 7) * 4];
            p[0] = v.x; p[1] = v.y; p[2] = v.z; p[3] = v.w;
        }
    }
#pragma unroll
    for (int j = 0; j < 2; ++j) {
        int idx = tid + (j << 8);
        int row = idx >> 5, d = idx & 31;
        sQ[row * 34 + d] = g_Q[h * 32768 + (b0 + row) * 32 + d];
    }
    if (tid < 64) {
        int t = tid >> 5, d = tid & 31;
        sKE[tid] = g_KE[t * 256 + h * 32 + d];
        sVE[tid] = g_VE[t * 256 + h * 32 + d];
    }
    __syncthreads();

    // qe[row][t] = Q[row].KE[t]
    if (tid < 32) {
        int rr = tid >> 1, t = tid & 1;
        float a = 0.f;
#pragma unroll
        for (int d = 0; d < 32; ++d) a += sQ[rr * 34 + d] * sKE[t * 32 + d];
        sqe[rr * 2 + t] = a;
    }
    __syncthreads();

    // masks + qe + q into registers
    unsigned vb[4], tb[4];
    float qe0[4], qe1[4];
    unsigned long long q2[4][16];
#pragma unroll
    for (int r = 0; r < 4; ++r) {
        int row = b0 + rbase + r;
        vb[r] = g_mba[(row * 2 + half) * 32 + l];
        tb[r] = g_mbt[(row * 2 + half) * 32 + l];
        qe0[r] = sqe[(rbase + r) * 2 + 0];
        qe1[r] = sqe[(rbase + r) * 2 + 1];
#pragma unroll
        for (int p = 0; p < 16; ++p)
            q2[r][p] = *reinterpret_cast<const unsigned long long*>(
                &sQ[(rbase + r) * 34 + 2 * p]);
    }

    // ---- scores ----
    float rmax[4] = {-3.0e38f, -3.0e38f, -3.0e38f, -3.0e38f};
#pragma unroll 2
    for (int ii = 0; ii < 16; ++ii) {
        int n = nb + (ii << 5);
        const float* kp = &sK[n * 34];
        unsigned long long a0 = 0, a1 = 0, a2 = 0, a3 = 0;
#pragma unroll
        for (int p = 0; p < 16; ++p) {
            unsigned long long kv = *reinterpret_cast<const unsigned long long*>(&kp[2 * p]);
            FMA2(a0, q2[0][p], kv);
            FMA2(a1, q2[1][p], kv);
            FMA2(a2, q2[2][p], kv);
            FMA2(a3, q2[3][p], kv);
        }
        float2 f0 = unpack2(a0), f1 = unpack2(a1), f2 = unpack2(a2), f3 = unpack2(a3);
        float s0 = f0.x + f0.y + (((tb[0] >> ii) & 1u) ? qe1[0] : qe0[0]);
        float s1 = f1.x + f1.y + (((tb[1] >> ii) & 1u) ? qe1[1] : qe0[1]);
        float s2 = f2.x + f2.y + (((tb[2] >> ii) & 1u) ? qe1[2] : qe0[2]);
        float s3 = f3.x + f3.y + (((tb[3] >> ii) & 1u) ? qe1[3] : qe0[3]);
        sS[(rbase + 0) * 1024 + n] = s0;
        sS[(rbase + 1) * 1024 + n] = s1;
        sS[(rbase + 2) * 1024 + n] = s2;
        sS[(rbase + 3) * 1024 + n] = s3;
        if ((vb[0] >> ii) & 1u) rmax[0] = fmaxf(rmax[0], s0);
        if ((vb[1] >> ii) & 1u) rmax[1] = fmaxf(rmax[1], s1);
        if ((vb[2] >> ii) & 1u) rmax[2] = fmaxf(rmax[2], s2);
        if ((vb[3] >> ii) & 1u) rmax[3] = fmaxf(rmax[3], s3);
    }
#pragma unroll
    for (int s = 16; s; s >>= 1)
#pragma unroll
        for (int r = 0; r < 4; ++r)
            rmax[r] = fmaxf(rmax[r], __shfl_xor_sync(0xffffffffu, rmax[r], s));
    if (l == 0)
#pragma unroll
        for (int r = 0; r < 4; ++r) smax[(rbase + r) * 2 + half] = rmax[r];
    __syncthreads();   // also: everyone done reading sK

    float rm[4];
#pragma unroll
    for (int r = 0; r < 4; ++r)
        rm[r] = fmaxf(smax[(rbase + r) * 2], smax[(rbase + r) * 2 + 1]);

    // ---- load V into sK (overlaps with exp pass below) ----
    {
        const float4* src = reinterpret_cast<const float4*>(g_V + h * 32768);
#pragma unroll
        for (int it = 0; it < 32; ++it) {
            int idx = tid + (it << 8);
            float4 v = src[idx];
            float* p = &sK[(idx >> 3) * 34 + (idx & 7) * 4];
            p[0] = v.x; p[1] = v.y; p[2] = v.z; p[3] = v.w;
        }
    }

    // ---- exp + row sums ----
    float rsum[4] = {0.f, 0.f, 0.f, 0.f};
    float rw1[4] = {0.f, 0.f, 0.f, 0.f};
#pragma unroll 2
    for (int ii = 0; ii < 16; ++ii) {
        int n = nb + (ii << 5);
#pragma unroll
        for (int r = 0; r < 4; ++r) {
            float s = sS[(rbase + r) * 1024 + n];
            float p = ((vb[r] >> ii) & 1u) ? __expf(s - rm[r]) : 0.f;
            sS[(rbase + r) * 1024 + n] = p;
            rsum[r] += p;
            if ((tb[r] >> ii) & 1u) rw1[r] += p;
        }
    }
#pragma unroll
    for (int s = 16; s; s >>= 1)
#pragma unroll
        for (int r = 0; r < 4; ++r) {
            rsum[r] += __shfl_xor_sync(0xffffffffu, rsum[r], s);
            rw1[r]  += __shfl_xor_sync(0xffffffffu, rw1[r], s);
        }
    if (l == 0)
#pragma unroll
        for (int r = 0; r < 4; ++r) {
            ssum[(rbase + r) * 2 + half] = rsum[r];
            sw1[(rbase + r) * 2 + half]  = rw1[r];
        }
    __syncthreads();   // V loaded, attn in sS, sums published

    float inv[4];
#pragma unroll
    for (int r = 0; r < 4; ++r) {
        float st = ssum[(rbase + r) * 2] + ssum[(rbase + r) * 2 + 1];
        inv[r] = st > 0.f ? 1.f / st : 0.f;
    }

    // ---- AV: acc2[r][p] covers d = 2p, 2p+1 ----
    unsigned long long acc[4][16];
#pragma unroll
    for (int r = 0; r < 4; ++r)
#pragma unroll
        for (int p = 0; p < 16; ++p) acc[r][p] = 0ull;

#pragma unroll 1
    for (int ii = 0; ii < 16; ++ii) {
        int n = nb + (ii << 5);
        const float* vp = &sK[n * 34];
        unsigned long long ab0 = bcast2(sS[(rbase + 0) * 1024 + n] * inv[0]);
        unsigned long long ab1 = bcast2(sS[(rbase + 1) * 1024 + n] * inv[1]);
        unsigned long long ab2 = bcast2(sS[(rbase + 2) * 1024 + n] * inv[2]);
        unsigned long long ab3 = bcast2(sS[(rbase + 3) * 1024 + n] * inv[3]);
#pragma unroll
        for (int p = 0; p < 16; ++p) {
            unsigned long long vv = *reinterpret_cast<const unsigned long long*>(&vp[2 * p]);
            FMA2(acc[0][p], ab0, vv);
            FMA2(acc[1][p], ab1, vv);
            FMA2(acc[2][p], ab2, vv);
            FMA2(acc[3][p], ab3, vv);
        }
    }
    __syncthreads();   // all done reading V -> sK reusable as reduction buffer

    // ---- cross-thread reduction: red[src][out], stride 513 (conflict-free) ----
    {
        const int src = half * 32 + l;
#pragma unroll
        for (int r = 0; r < 4; ++r)
#pragma unroll
            for (int p = 0; p < 16; ++p) {
                float2 f = unpack2(acc[r][p]);
                int o = (rbase + r) * 32 + 2 * p;
                sK[src * 513 + o]     = f.x;
                sK[src * 513 + o + 1] = f.y;
            }
    }
    __syncthreads();

#pragma unroll
    for (int j = 0; j < 2; ++j) {
        int o = tid + (j << 8);
        int row = o >> 5, d = o & 31;
        float a0 = 0.f, a1 = 0.f, a2 = 0.f, a3 = 0.f;
#pragma unroll
        for (int s = 0; s < 64; s += 4) {
            a0 += sK[(s + 0) * 513 + o];
            a1 += sK[(s + 1) * 513 + o];
            a2 += sK[(s + 2) * 513 + o];
            a3 += sK[(s + 3) * 513 + o];
        }
        float st = ssum[row * 2] + ssum[row * 2 + 1];
        float w1t = sw1[row * 2] + sw1[row * 2 + 1];
        float invT = st > 0.f ? 1.f / st : 0.f;
        float w1 = w1t * invT;
        float w0 = (st - w1t) * invT;
        float oval = a0 + a1 + a2 + a3 + w0 * sVE[d] + w1 * sVE[32 + d];
        g_AO[(b0 + row) * 256 + h * 32 + d] = oval;
    }
}

// ---------------------------------------------------------------------------
extern "C" void kernel_launch(void* const* d_in, const int* in_sizes, int n_in,
                              void* d_out, int out_size)
{
    const float* h_target = (const float*)d_in[0];
    const float* h_neigh  = (const float*)d_in[1];
    const int*   adjacency = (const int*)d_in[2];
    const int*   edge_types = (const int*)d_in[3];
    const float* Wq = (const float*)d_in[4];
    const float* bq = (const float*)d_in[5];
    const float* Wk = (const float*)d_in[6];
    const float* bk = (const float*)d_in[7];
    const float* Wv = (const float*)d_in[8];
    const float* bv = (const float*)d_in[9];
    const float* Wo = (const float*)d_in[10];
    const float* bo = (const float*)d_in[11];
    const float* E  = (const float*)d_in[12];
    float* out = (float*)d_out;

    const int attn_smem = (SK_F + SS_F + SQ_F + 32 + 64 + 64 + 32 + 32 + 32) * 4; // 208000 B
    static int smem_set = 0;
    if (!smem_set) {
        cudaFuncSetAttribute(attn_kernel, cudaFuncAttributeMaxDynamicSharedMemorySize,
                             attn_smem);
        smem_set = 1;
    }

    pack_kernel<<<256, 256>>>(adjacency, edge_types);
    qkv_kernel<<<dim3(32, 4, 3), 128>>>(h_target, h_neigh, Wq, bq, Wk, bk, Wv, bv);
    edge_kernel<<<4, 256>>>(E, Wk, Wv);
    attn_kernel<<<dim3(64, 8), 256, attn_smem>>>();
    proj_kernel<<<dim3(32, 4), 128>>>(Wo, bo, out);
}